// round 10
// baseline (speedup 1.0000x reference)
#include <cuda_runtime.h>
#include <math.h>

#define T_STEPS 1000
#define NS 10
#define NTRAJ 256
#define CHUNKS 100
#define CLEN 10

#define TRAJ_STRIDE (NS*(T_STEPS+1))            /* 10010 floats per trajectory */
#define OUT_TRAJ_SIZE (NTRAJ*TRAJ_STRIDE)       /* 2,562,560 */
#define OUT_PK_OFF   OUT_TRAJ_SIZE
#define OUT_PK_SIZE  (NTRAJ*(T_STEPS+1)*NS*NS)  /* 25,625,600 */
#define OUT_MSE_OFF  (OUT_PK_OFF+OUT_PK_SIZE)   /* 28,188,160 */

#define DONE_V (T_STEPS + 2)                    /* progress sentinel, > any need */

// stage1 role geometry: [0]=riccati, [1..501]=pk (t pairs), [502..601]=chunkmat,
// [602..1701]=chunkv
#define B_PK0   1
#define N_PK    501
#define B_CM0   (B_PK0 + N_PK)      /* 502 */
#define B_CV0   (B_CM0 + CHUNKS)    /* 602 */
#define NB_S1   (B_CV0 + CHUNKS*11) /* 1702 */

// stage2 role geometry: [0..10]=chainscan producers, [11..1110]=replay consumers
#define NB_CS   11
#define NB_S2   (NB_CS + CHUNKS*11) /* 1111 */

// -------- scratch (no allocations allowed) --------
__device__ __align__(16) float d_Amat[T_STEPS*100];   // A_t = (I - K_t H) F  (valid to tconv)
__device__ __align__(16) float d_Kmat[T_STEPS*100];   // K_t                  (valid to tconv)
__device__ __align__(16) float d_Pp  [T_STEPS*100];   // P_pos_t              (valid to tconv)
__device__ int d_tconv;
__device__ int d_progress;                            // riccati step progress (monotone)
__device__ int d_ccount[CHUNKS];                      // chainscan arrivals per chunk (monotone)
__device__ __align__(16) float d_Mc  [CHUNKS*100];      // chunk products
__device__ __align__(16) float d_Vc  [CHUNKS*NTRAJ*NS]; // chunk-local affine constants
__device__ __align__(16) float d_Xst [CHUNKS*NTRAJ*NS]; // state at chunk starts
__device__ float d_partial[CHUNKS*NTRAJ];               // per (chunk,traj) sq-error sums

// 10-term dot product with 4 accumulators (short dependency chains)
#define DOT10(EXPR_A, EXPR_B, OUTV)                                            \
    do {                                                                       \
        float a0=0.f,a1=0.f,a2=0.f,a3=0.f;                                     \
        { const int j=0; a0 += (EXPR_A)*(EXPR_B); }                            \
        { const int j=1; a1 += (EXPR_A)*(EXPR_B); }                            \
        { const int j=2; a2 += (EXPR_A)*(EXPR_B); }                            \
        { const int j=3; a3 += (EXPR_A)*(EXPR_B); }                            \
        { const int j=4; a0 += (EXPR_A)*(EXPR_B); }                            \
        { const int j=5; a1 += (EXPR_A)*(EXPR_B); }                            \
        { const int j=6; a2 += (EXPR_A)*(EXPR_B); }                            \
        { const int j=7; a3 += (EXPR_A)*(EXPR_B); }                            \
        { const int j=8; a0 += (EXPR_A)*(EXPR_B); }                            \
        { const int j=9; a1 += (EXPR_A)*(EXPR_B); }                            \
        OUTV = (a0+a1)+(a2+a3);                                                \
    } while (0)

// -------- flag ops --------
__device__ __forceinline__ int ld_acq(const int* p) {
    int v;
    asm volatile("ld.acquire.gpu.b32 %0, [%1];" : "=r"(v) : "l"(p) : "memory");
    return v;
}
__device__ __forceinline__ void st_rel(int* p, int v) {
    asm volatile("st.release.gpu.b32 [%0], %1;" :: "l"(p), "r"(v) : "memory");
}
__device__ __forceinline__ int wait_prog(int need) {
    int p = ld_acq(&d_progress);
    while (p < need) { __nanosleep(128); p = ld_acq(&d_progress); }
    return p;
}
__device__ __forceinline__ void wait_count(const int* p, int need) {
    int v = ld_acq(p);
    while (v < need) { __nanosleep(128); v = ld_acq(p); }
}

// ---------------------------------------------------------------------------
// group-of-10 affine step: lane holds x[row]; matvec via shuffles.
// ---------------------------------------------------------------------------
__device__ __forceinline__ float group_step(const float* __restrict__ Kl,
                                            const float* __restrict__ Al,
                                            float y, float x, int sub, int row)
{
    float sk = 0.f, sa = 0.f;
    #pragma unroll
    for (int j = 0; j < 10; ++j) {
        float yj = __shfl_sync(0xffffffffu, y, sub*10 + j);
        float xj = __shfl_sync(0xffffffffu, x, sub*10 + j);
        sk += Kl[row*10 + j] * yj;
        sa += Al[row*10 + j] * xj;
    }
    return sk + sa;
}

// ============================================================================
// stage1: producer/consumer megakernel (riccati + pk + chunkmat + chunkv).
// ============================================================================
__global__ __launch_bounds__(256) void stage1_kernel(
    const float* __restrict__ Fg, const float* __restrict__ Hg,
    const float* __restrict__ Qg, const float* __restrict__ Rg,
    const float* __restrict__ Y,
    float* __restrict__ out, int out_size)
{
    __shared__ float smu[2000];   // 8 KB union across roles
    const int b = blockIdx.x;
    const int tid = threadIdx.x;

    if (b == 0) {
        // ------------------- riccati producer -------------------
        float* Fs  = smu + 0;    float* Hs  = smu + 100;
        float* HFs = smu + 200;  float* Gs  = smu + 300;
        float* QHT = smu + 400;  float* P   = smu + 500;
        float* FP  = smu + 600;  float* Pn  = smu + 700;
        float* W   = smu + 800;  float* Ssh = smu + 900;
        float* Sinv= smu + 1000; float* Ks  = smu + 1100;

        const int r = tid / 10, c = tid % 10;
        const bool act = tid < 100;
        float qv = 0.f, rv = 0.f;

        if (act) { Fs[tid] = Fg[tid]; Hs[tid] = Hg[tid]; }
        __syncthreads();
        if (act) {
            qv = Qg[tid]; rv = Rg[tid];
            float s;
            DOT10(Hs[r*10+j], Fs[j*10+c], s);      // HF = H F
            HFs[tid] = s;
            float g;
            DOT10(Fs[j*10+r], Hs[c*10+j], g);      // G[r][c] = sum F[k][r] H[c][k]
            Gs[tid] = g;
            float q;
            DOT10(Qg[r*10+j], Hs[c*10+j], q);      // QHT = Q H^T
            QHT[tid] = q;
            P[tid] = (r == c) ? 1.f : 0.f;
        }
        __syncthreads();

        int conv = -1;
        for (int t = 0; t < T_STEPS; ++t) {
            if (act) { float s; DOT10(Fs[r*10+j], P[j*10+c], s); FP[tid] = s; }
            __syncthreads();
            if (act) {
                float sp, sw;
                DOT10(FP[r*10+j], Fs[c*10+j], sp);
                DOT10(FP[r*10+j], Gs[j*10+c], sw);
                Pn[tid] = sp + qv;
                W[tid]  = sw + QHT[tid];
            }
            __syncthreads();
            if (act) { float s; DOT10(Hs[r*10+j], W[j*10+c], s); Ssh[tid] = s + rv; }
            __syncthreads();
            if (tid < 32) {
                const int lr = (tid < 10) ? tid : 0;
                float sv[10];
                #pragma unroll
                for (int j = 0; j < 10; ++j) sv[j] = Ssh[lr*10+j];
                #pragma unroll
                for (int k = 0; k < 10; ++k) {
                    float rk[10];
                    #pragma unroll
                    for (int j = 0; j < 10; ++j)
                        rk[j] = __shfl_sync(0xffffffffu, sv[j], k);
                    float pinv = 1.0f / rk[k];
                    if (tid == k) {
                        #pragma unroll
                        for (int j = 0; j < 10; ++j) sv[j] = rk[j] * pinv;
                        sv[k] = pinv;
                    } else {
                        float f = sv[k] * pinv;
                        #pragma unroll
                        for (int j = 0; j < 10; ++j)
                            if (j != k) sv[j] -= f * rk[j];
                        sv[k] = -f;
                    }
                }
                if (tid < 10) {
                    #pragma unroll
                    for (int j = 0; j < 10; ++j) Sinv[tid*10+j] = sv[j];
                }
            }
            __syncthreads();
            if (act) { float s; DOT10(W[r*10+j], Sinv[j*10+c], s); Ks[tid] = s; }
            __syncthreads();
            bool pred = false;
            if (act) {
                float s1, s2, sa;
                DOT10(Ks[r*10+j], W[c*10+j], s1);
                DOT10(W[r*10+j], Ks[c*10+j], s2);
                DOT10(Ks[r*10+j], HFs[j*10+c], sa);
                float pnew = Pn[tid] - 0.5f * (s1 + s2);
                float aval = Fs[tid] - sa;
                pred = fabsf(pnew - P[tid]) > 1e-5f;
                d_Pp  [t*100 + tid] = pnew;
                d_Kmat[t*100 + tid] = Ks[tid];
                d_Amat[t*100 + tid] = aval;
                P[tid] = pnew;
            }
            bool allconv = !__syncthreads_or(pred);
            if (allconv) {
                if (tid == 0) {
                    d_tconv = t;
                    __threadfence();
                    st_rel(&d_progress, DONE_V);
                }
                conv = t;
                break;
            } else if (tid == 0) {
                __threadfence();
                st_rel(&d_progress, t + 1);
            }
        }
        if (conv < 0 && tid == 0) {
            d_tconv = T_STEPS - 1;
            __threadfence();
            st_rel(&d_progress, DONE_V);
        }
        return;
    }

    if (b < B_CM0) {
        // ------------------- pk role: time pair (t0, t0+1) -------------------
        const int pkb = b - B_PK0;             // 0..500
        const int t0  = 2 * pkb;               // 0,2,...,1000
        const int tcount = (t0 + 1 <= T_STEPS) ? 2 : 1;
        int need = t0 + tcount - 1;
        if (need < 1) need = 1;
        int p = wait_prog(need);
        const int tcv = (p >= DONE_V) ? d_tconv : (T_STEPS - 1);

        if (pkb == 0 && out_size >= OUT_TRAJ_SIZE) {
            for (int i = tid; i < NTRAJ*NS; i += 256) {
                int traj = i / NS, e = i % NS;
                out[(size_t)traj*TRAJ_STRIDE + e] = 0.f;
            }
        }

        const int per = 25 * tcount;
        const int total = NTRAJ * per;
        for (int idx = tid; idx < total; idx += 256) {
            int traj = idx / per;
            int rem  = idx % per;
            int tloc = rem / 25;
            int e4   = rem % 25;
            int t = t0 + tloc;
            long f = (long)OUT_PK_OFF + ((long)traj*(T_STEPS+1) + t)*100 + e4*4;
            if (f + 4 <= (long)out_size) {
                float4 v;
                if (t == 0) v = make_float4(0.f, 0.f, 0.f, 0.f);
                else        v = *(const float4*)&d_Pp[min(t-1, tcv)*100 + e4*4];
                *(float4*)(out + f) = v;
            }
        }
        return;
    }

    if (b < B_CV0) {
        // ------------------- chunkmat role -------------------
        const int chunk = b - B_CM0;
        int p = wait_prog(chunk*CLEN + CLEN);
        const int tcv = (p >= DONE_V) ? d_tconv : (T_STEPS - 1);

        float* sA = smu;            // 1000
        float* Mb = smu + 1000;     // 200
        for (int i = tid; i < CLEN*100; i += 256) {
            int l = i / 100, e = i % 100;
            int tc = min(chunk*CLEN + l, tcv);
            sA[i] = d_Amat[tc*100 + e];
        }
        __syncthreads();
        const int r = tid / 10, c = tid % 10;
        const bool act = tid < 100;
        if (act) Mb[tid] = sA[tid];
        __syncthreads();
        for (int l = 1; l < CLEN; ++l) {
            if (act) {
                float s = 0.f;
                #pragma unroll
                for (int j = 0; j < 10; ++j)
                    s += sA[l*100 + r*10+j] * Mb[((l-1)&1)*100 + j*10+c];
                Mb[(l&1)*100 + tid] = s;
            }
            __syncthreads();
        }
        if (act) d_Mc[chunk*100 + tid] = Mb[((CLEN-1)&1)*100 + tid];
        return;
    }

    // ------------------- chunkv role -------------------
    {
        const int idx = b - B_CV0;
        const int chunk = idx / 11;
        const int slice = idx % 11;
        int p = wait_prog(chunk*CLEN + CLEN);
        const int tcv = (p >= DONE_V) ? d_tconv : (T_STEPS - 1);

        float* sA = smu;            // 1000
        float* sK = smu + 1000;     // 1000
        for (int i = tid; i < CLEN*100; i += 256) {
            int l = i / 100, e = i % 100;
            int tc = min(chunk*CLEN + l, tcv);
            sA[i] = d_Amat[tc*100 + e];
            sK[i] = d_Kmat[tc*100 + e];
        }
        __syncthreads();

        const int warpId = tid / 32, lane = tid % 32;
        const int sub = lane / 10, row = lane - sub*10;
        const int g = slice*24 + warpId*3 + sub;
        const bool valid = (lane < 30) && (g < NTRAJ);
        const int traj = valid ? g : 0;

        float v = 0.f;
        const float* yb = Y + (size_t)traj * (T_STEPS*NS) + chunk*CLEN*NS;
        #pragma unroll
        for (int l = 0; l < CLEN; ++l) {
            float y = yb[l*10 + row];
            v = group_step(&sK[l*100], &sA[l*100], y, v, sub, row);
        }
        if (valid)
            d_Vc[((size_t)chunk*NTRAJ + traj)*NS + row] = v;
    }
}

// ============================================================================
// stage2: chainscan producers (blocks 0..10) + replay consumers (11..1110).
// Producers publish per-chunk arrival counts; replay of chunk c starts as soon
// as all 11 producers have stored d_Xst for chunk c.
// ============================================================================
__global__ __launch_bounds__(256) void stage2_kernel(
    const float* __restrict__ Y, const float* __restrict__ X,
    float* __restrict__ out, int out_size)
{
    const int b = blockIdx.x;
    const int tid = threadIdx.x;

    if (b < NB_CS) {
        // ------------------- chainscan producer -------------------
        __shared__ float Ms[CHUNKS*100];   // 40 KB
        {
            const float4* src = (const float4*)d_Mc;
            float4* dst = (float4*)Ms;
            for (int i = tid; i < CHUNKS*100/4; i += blockDim.x) dst[i] = src[i];
        }
        __syncthreads();

        const int warpId = tid / 32, lane = tid % 32;
        const int sub = lane / 10, row = lane - sub*10;
        const int traj = (b * (256/32) + warpId) * 3 + sub;
        const bool valid = (lane < 30) && (traj < NTRAJ);

        float x = 0.f;
        for (int ch = 0; ch < CHUNKS; ++ch) {
            if (valid) d_Xst[((size_t)ch*NTRAJ + traj)*NS + row] = x;
            __syncthreads();                // all warps stored chunk ch
            if (tid == 0) {
                __threadfence();            // make Xst visible
                atomicAdd(&d_ccount[ch], 1);
            }
            float v = valid ? d_Vc[((size_t)ch*NTRAJ + traj)*NS + row] : 0.f;
            float xn = v;
            #pragma unroll
            for (int j = 0; j < 10; ++j)
                xn += Ms[ch*100 + row*10 + j] *
                      __shfl_sync(0xffffffffu, x, sub*10 + j);
            x = xn;
        }
        return;
    }

    // ------------------- replay consumer -------------------
    {
        __shared__ float sA[CLEN*100];
        __shared__ float sK[CLEN*100];
        const int idx = b - NB_CS;
        const int chunk = idx / 11;
        const int slice = idx % 11;
        const int tconv = d_tconv;

        for (int i = tid; i < CLEN*100; i += blockDim.x) {
            int l = i / 100, e = i % 100;
            int tc = min(chunk*CLEN + l, tconv);
            sA[i] = d_Amat[tc*100 + e];
            sK[i] = d_Kmat[tc*100 + e];
        }
        __syncthreads();

        // wait for all 11 chainscan producers to publish chunk's start states
        wait_count(&d_ccount[chunk], NB_CS);

        const int warpId = tid / 32, lane = tid % 32;
        const int sub = lane / 10, row = lane - sub*10;
        const int g = slice*24 + warpId*3 + sub;
        const bool valid = (lane < 30) && (g < NTRAJ);
        const int traj = valid ? g : 0;

        float x = d_Xst[((size_t)chunk*NTRAJ + traj)*NS + row];

        const bool wr = valid && (out_size >= OUT_TRAJ_SIZE);
        float errsum = 0.f;
        const float* yb = Y + (size_t)traj * (T_STEPS*NS);
        const float* xb = X + (size_t)traj * TRAJ_STRIDE;
        float* ob = out + (size_t)traj * TRAJ_STRIDE;

        #pragma unroll
        for (int l = 0; l < CLEN; ++l) {
            const int t = chunk*CLEN + l;
            float y = yb[t*10 + row];
            x = group_step(&sK[l*100], &sA[l*100], y, x, sub, row);
            if (wr) ob[(t+1)*10 + row] = x;
            float d = xb[(t+1)*10 + row] - x;
            errsum += d * d;
        }

        float tot = 0.f;
        #pragma unroll
        for (int j = 0; j < 10; ++j)
            tot += __shfl_sync(0xffffffffu, errsum, sub*10 + j);
        if (valid && row == 0)
            d_partial[(size_t)chunk*NTRAJ + traj] = tot;
    }
}

// ============================================================================
// mse: 1024 threads, 4 lanes per trajectory (25 coalesced loads each),
// shfl reduce within the 4-lane group, then block tree over 256 dB values.
// ============================================================================
__global__ __launch_bounds__(1024) void mse_kernel(float* __restrict__ out, int out_size)
{
    __shared__ float red[NTRAJ];
    const int tid = threadIdx.x;
    const int traj = tid >> 2;
    const int lane4 = tid & 3;

    float s = 0.f;
    #pragma unroll
    for (int c = 0; c < CHUNKS/4; ++c)
        s += d_partial[(size_t)(c*4 + lane4)*NTRAJ + traj];
    s += __shfl_xor_sync(0xffffffffu, s, 1);
    s += __shfl_xor_sync(0xffffffffu, s, 2);
    if (lane4 == 0)
        red[traj] = 10.f * log10f(s / (float)(T_STEPS * NS));
    __syncthreads();
    for (int off = NTRAJ/2; off > 0; off >>= 1) {
        if (tid < off) red[tid] += red[tid + off];
        __syncthreads();
    }
    if (tid == 0 && OUT_MSE_OFF < out_size)
        out[OUT_MSE_OFF] = red[0] / (float)NTRAJ;
}

// ============================================================================
extern "C" void kernel_launch(void* const* d_in, const int* in_sizes, int n_in,
                              void* d_out, int out_size)
{
    const float* X = (const float*)d_in[0];
    const float* Y = (const float*)d_in[1];
    const float* F = (const float*)d_in[2];
    const float* H = (const float*)d_in[3];
    const float* Q = (const float*)d_in[4];
    const float* R = (const float*)d_in[5];
    float* out = (float*)d_out;

    stage1_kernel<<<NB_S1, 256>>>(F, H, Q, R, Y, out, out_size);
    stage2_kernel<<<NB_S2, 256>>>(Y, X, out, out_size);
    mse_kernel   <<<1, 1024>>>(out, out_size);
}

// round 12
// speedup vs baseline: 2.3477x; 2.3477x over previous
#include <cuda_runtime.h>
#include <math.h>

#define T_STEPS 1000
#define NS 10
#define NTRAJ 256
#define CHUNKS 100
#define CLEN 10

#define TRAJ_STRIDE (NS*(T_STEPS+1))            /* 10010 floats per trajectory */
#define OUT_TRAJ_SIZE (NTRAJ*TRAJ_STRIDE)       /* 2,562,560 */
#define OUT_PK_OFF   OUT_TRAJ_SIZE
#define OUT_PK_SIZE  (NTRAJ*(T_STEPS+1)*NS*NS)  /* 25,625,600 */
#define OUT_MSE_OFF  (OUT_PK_OFF+OUT_PK_SIZE)   /* 28,188,160 */

// fused_mid launch geometry
#define NB_V  1100     /* chunkv role blocks: 100 chunks x 11 slices          */
#define NB_M  100      /* chunkmat role blocks                                */
#define NB_PK 1200     /* pk role blocks                                      */
#define NB_MID 2400    /* even b -> compute(b/2), odd b -> pk(b/2)            */

// -------- scratch (no allocations allowed) --------
__device__ __align__(16) float d_Amat[T_STEPS*100];   // A_t = (I - K_t H) F  (valid to tconv)
__device__ __align__(16) float d_Kmat[T_STEPS*100];   // K_t                  (valid to tconv)
__device__ __align__(16) float d_Pp  [T_STEPS*100];   // P_pos_t              (valid to tconv)
__device__ int d_tconv;
__device__ __align__(16) float d_Mc  [CHUNKS*100];      // chunk products
__device__ __align__(16) float d_Vc  [CHUNKS*NTRAJ*NS]; // chunk-local affine constants
__device__ __align__(16) float d_Xst [CHUNKS*NTRAJ*NS]; // state at chunk starts
__device__ float d_partial[CHUNKS*NTRAJ];               // per (chunk,traj) sq-error sums

// 10-term dot product with 4 accumulators (short dependency chains)
#define DOT10(EXPR_A, EXPR_B, OUTV)                                            \
    do {                                                                       \
        float a0=0.f,a1=0.f,a2=0.f,a3=0.f;                                     \
        { const int j=0; a0 += (EXPR_A)*(EXPR_B); }                            \
        { const int j=1; a1 += (EXPR_A)*(EXPR_B); }                            \
        { const int j=2; a2 += (EXPR_A)*(EXPR_B); }                            \
        { const int j=3; a3 += (EXPR_A)*(EXPR_B); }                            \
        { const int j=4; a0 += (EXPR_A)*(EXPR_B); }                            \
        { const int j=5; a1 += (EXPR_A)*(EXPR_B); }                            \
        { const int j=6; a2 += (EXPR_A)*(EXPR_B); }                            \
        { const int j=7; a3 += (EXPR_A)*(EXPR_B); }                            \
        { const int j=8; a0 += (EXPR_A)*(EXPR_B); }                            \
        { const int j=9; a1 += (EXPR_A)*(EXPR_B); }                            \
        OUTV = (a0+a1)+(a2+a3);                                                \
    } while (0)

// ============================================================================
// Kernel 1: serial Riccati recursion (single block, runs ALONE — R10 showed
// co-scheduling bulk work with this serial producer costs ~2x; keep isolated).
//   FP = F P ; Pn = FP F^T + Q ; W = FP G + Q H^T  (G = F^T H^T)
//   S = H W + R ; K = W S^-1 ; P_pos = Pn - sym(K W^T) ; A = F - K (H F)
// ============================================================================
__global__ void riccati_kernel(const float* __restrict__ Fg,
                               const float* __restrict__ Hg,
                               const float* __restrict__ Qg,
                               const float* __restrict__ Rg)
{
    __shared__ float Fs[100], Hs[100], HFs[100], Gs[100], QHT[100];
    __shared__ float P[100], FP[100], Pn[100], W[100], Ssh[100], Sinv[100], Ks[100];

    const int tid = threadIdx.x;
    const int r = tid / 10, c = tid % 10;
    const bool act = tid < 100;
    float qv = 0.f, rv = 0.f;

    if (act) { Fs[tid] = Fg[tid]; Hs[tid] = Hg[tid]; }
    __syncthreads();
    if (act) {
        qv = Qg[tid]; rv = Rg[tid];
        float s;
        DOT10(Hs[r*10+j], Fs[j*10+c], s);      // HF = H F
        HFs[tid] = s;
        float g;
        DOT10(Fs[j*10+r], Hs[c*10+j], g);      // G[r][c] = sum_k F[k][r] H[c][k]
        Gs[tid] = g;
        float q;
        DOT10(Qg[r*10+j], Hs[c*10+j], q);      // QHT = Q H^T
        QHT[tid] = q;
        P[tid] = (r == c) ? 1.f : 0.f;
    }
    __syncthreads();

    int tconv = T_STEPS - 1;
    for (int t = 0; t < T_STEPS; ++t) {
        // FP = F * P
        if (act) { float s; DOT10(Fs[r*10+j], P[j*10+c], s); FP[tid] = s; }
        __syncthreads();
        // fused: Pn = FP F^T + Q ; W = FP G + QHT
        if (act) {
            float sp, sw;
            DOT10(FP[r*10+j], Fs[c*10+j], sp);
            DOT10(FP[r*10+j], Gs[j*10+c], sw);
            Pn[tid] = sp + qv;
            W[tid]  = sw + QHT[tid];
        }
        __syncthreads();
        // S = H W + R
        if (act) { float s; DOT10(Hs[r*10+j], W[j*10+c], s); Ssh[tid] = s + rv; }
        __syncthreads();
        // in-warp Gauss-Jordan inverse of S
        if (tid < 32) {
            const int lr = (tid < 10) ? tid : 0;
            float sv[10];
            #pragma unroll
            for (int j = 0; j < 10; ++j) sv[j] = Ssh[lr*10+j];
            #pragma unroll
            for (int k = 0; k < 10; ++k) {
                float rk[10];
                #pragma unroll
                for (int j = 0; j < 10; ++j)
                    rk[j] = __shfl_sync(0xffffffffu, sv[j], k);
                float pinv = 1.0f / rk[k];
                if (tid == k) {
                    #pragma unroll
                    for (int j = 0; j < 10; ++j) sv[j] = rk[j] * pinv;
                    sv[k] = pinv;
                } else {
                    float f = sv[k] * pinv;
                    #pragma unroll
                    for (int j = 0; j < 10; ++j)
                        if (j != k) sv[j] -= f * rk[j];
                    sv[k] = -f;
                }
            }
            if (tid < 10) {
                #pragma unroll
                for (int j = 0; j < 10; ++j) Sinv[tid*10+j] = sv[j];
            }
        }
        __syncthreads();
        // K = W * Sinv
        if (act) { float s; DOT10(W[r*10+j], Sinv[j*10+c], s); Ks[tid] = s; }
        __syncthreads();
        // fused: Pnew = Pn - sym(K W^T), A = F - K*HF, store, converge
        bool pred = false;
        if (act) {
            float s1, s2, sa;
            DOT10(Ks[r*10+j], W[c*10+j], s1);
            DOT10(W[r*10+j], Ks[c*10+j], s2);
            DOT10(Ks[r*10+j], HFs[j*10+c], sa);
            float pnew = Pn[tid] - 0.5f * (s1 + s2);
            float aval = Fs[tid] - sa;
            pred = fabsf(pnew - P[tid]) > 1e-5f;
            d_Pp  [t*100 + tid] = pnew;
            d_Kmat[t*100 + tid] = Ks[tid];
            d_Amat[t*100 + tid] = aval;
            P[tid] = pnew;
        }
        if (!__syncthreads_or(pred)) { tconv = t; break; }
    }
    if (tid == 0) d_tconv = tconv;
}

// ---------------------------------------------------------------------------
// group-of-10 affine step: lane holds x[row]; matvec via shuffles.
// ---------------------------------------------------------------------------
__device__ __forceinline__ float group_step(const float* __restrict__ Kl,
                                            const float* __restrict__ Al,
                                            float y, float x, int sub, int row)
{
    float sk = 0.f, sa = 0.f;
    #pragma unroll
    for (int j = 0; j < 10; ++j) {
        float yj = __shfl_sync(0xffffffffu, y, sub*10 + j);
        float xj = __shfl_sync(0xffffffffu, x, sub*10 + j);
        sk += Kl[row*10 + j] * yj;
        sa += Al[row*10 + j] * xj;
    }
    return sk + sa;
}

// ============================================================================
// Kernel 2 (fused launch): role-split blocks, interleaved so pk's DRAM stores
// overlap chunkv/chunkmat compute. All roles throughput-bound (no serial
// producer inside — safe to co-schedule).
// ============================================================================
__global__ void fused_mid_kernel(const float* __restrict__ Y,
                                 float* __restrict__ out, int out_size)
{
    __shared__ float sA[CLEN*100];
    __shared__ float sK[CLEN*100];
    const int b = blockIdx.x;
    const int tid = threadIdx.x;
    const int tconv = d_tconv;

    if (b & 1) {
        // ------------------- pk role -------------------
        const int pkb = b >> 1;
        long tg = (long)pkb * blockDim.x + tid;
        if (tg < NTRAJ*NS && out_size >= OUT_TRAJ_SIZE) {
            int traj = (int)(tg / NS), i = (int)(tg % NS);
            out[(size_t)traj*TRAJ_STRIDE + i] = 0.f;
        }
        if (out_size < OUT_PK_OFF + 4) return;
        long total4 = (long)OUT_PK_SIZE / 4;
        long lim4 = ((long)out_size - OUT_PK_OFF) / 4;
        if (lim4 < total4) total4 = lim4;
        float4* outp = (float4*)(out + OUT_PK_OFF);
        const long stride = (long)NB_PK * blockDim.x;
        for (long idx = tg; idx < total4; idx += stride) {
            int e4 = (int)(idx % 25);
            long rem = idx / 25;
            int t = (int)(rem % (T_STEPS + 1));
            float4 v;
            if (t == 0) v = make_float4(0.f, 0.f, 0.f, 0.f);
            else {
                int tc = min(t - 1, tconv);
                v = *(const float4*)&d_Pp[tc*100 + e4*4];
            }
            outp[idx] = v;
        }
        return;
    }

    const int idx = b >> 1;
    if (idx < NB_V) {
        // ------------------- chunkv role -------------------
        const int chunk = idx / 11;
        const int slice = idx % 11;
        for (int i = tid; i < CLEN*100; i += blockDim.x) {
            int l = i / 100, e = i % 100;
            int tc = min(chunk*CLEN + l, tconv);
            sA[i] = d_Amat[tc*100 + e];
            sK[i] = d_Kmat[tc*100 + e];
        }
        __syncthreads();

        const int warpId = tid / 32, lane = tid % 32;
        const int sub = lane / 10, row = lane - sub*10;
        const int g = slice*24 + warpId*3 + sub;
        const bool valid = (lane < 30) && (g < NTRAJ);
        const int traj = valid ? g : 0;

        float v = 0.f;
        const float* yb = Y + (size_t)traj * (T_STEPS*NS) + chunk*CLEN*NS;
        #pragma unroll
        for (int l = 0; l < CLEN; ++l) {
            float y = yb[l*10 + row];
            v = group_step(&sK[l*100], &sA[l*100], y, v, sub, row);
        }
        if (valid)
            d_Vc[((size_t)chunk*NTRAJ + traj)*NS + row] = v;
    } else {
        // ------------------- chunkmat role -------------------
        const int chunk = idx - NB_V;
        for (int i = tid; i < CLEN*100; i += blockDim.x) {
            int l = i / 100, e = i % 100;
            int tc = min(chunk*CLEN + l, tconv);
            sA[i] = d_Amat[tc*100 + e];
        }
        __syncthreads();
        float* Mb = sK;   // reuse as Mb[2][100]
        const int r = tid / 10, c = tid % 10;
        const bool act = tid < 100;
        if (act) Mb[tid] = sA[tid];
        __syncthreads();
        for (int l = 1; l < CLEN; ++l) {
            if (act) {
                float s = 0.f;
                #pragma unroll
                for (int j = 0; j < 10; ++j)
                    s += sA[l*100 + r*10+j] * Mb[((l-1)&1)*100 + j*10+c];
                Mb[(l&1)*100 + tid] = s;
            }
            __syncthreads();
        }
        if (act) d_Mc[chunk*100 + tid] = Mb[((CLEN-1)&1)*100 + tid];
    }
}

// ============================================================================
// Kernel 3: serial chain over chunks (shuffle-based, barrier-free loop).
// Runs alone — latency-critical. grid=11, block=256.
// ============================================================================
#define CS_STEP(CH, VREG)                                                      \
    do {                                                                       \
        if (valid) d_Xst[((size_t)(CH)*NTRAJ + traj)*NS + row] = x;            \
        float xn = (VREG);                                                     \
        _Pragma("unroll")                                                      \
        for (int j = 0; j < 10; ++j)                                           \
            xn += Ms[(CH)*100 + row*10 + j] *                                  \
                  __shfl_sync(0xffffffffu, x, sub*10 + j);                     \
        x = xn;                                                                \
    } while (0)

__global__ void chainscan_kernel()
{
    __shared__ float Ms[CHUNKS*100];   // 40 KB
    const int tid = threadIdx.x;
    {
        const float4* src = (const float4*)d_Mc;
        float4* dst = (float4*)Ms;
        for (int i = tid; i < CHUNKS*100/4; i += blockDim.x) dst[i] = src[i];
    }
    __syncthreads();

    const int warpId = tid / 32, lane = tid % 32;
    const int sub = lane / 10, row = lane - sub*10;
    const int traj = (blockIdx.x * (blockDim.x/32) + warpId) * 3 + sub;
    const bool valid = (lane < 30) && (traj < NTRAJ);

    float x = 0.f;
    float vb0, vb1, vb2, vb3;
    #define LDV(CH) ((valid && (CH) < CHUNKS) ? d_Vc[((size_t)(CH)*NTRAJ + traj)*NS + row] : 0.f)
    vb0 = LDV(0); vb1 = LDV(1); vb2 = LDV(2); vb3 = LDV(3);
    for (int ch = 0; ch < CHUNKS; ch += 4) {
        CS_STEP(ch + 0, vb0); vb0 = LDV(ch + 4);
        CS_STEP(ch + 1, vb1); vb1 = LDV(ch + 5);
        CS_STEP(ch + 2, vb2); vb2 = LDV(ch + 6);
        CS_STEP(ch + 3, vb3); vb3 = LDV(ch + 7);
    }
    #undef LDV
}

// ============================================================================
// Kernel 4: replay (group-of-10 lanes). grid=(CHUNKS, 11), block=256.
// ============================================================================
__global__ void replay_kernel(const float* __restrict__ Y,
                              const float* __restrict__ X,
                              float* __restrict__ out, int out_size)
{
    __shared__ float sA[CLEN*100];
    __shared__ float sK[CLEN*100];
    const int chunk = blockIdx.x;
    const int slice = blockIdx.y;
    const int tid = threadIdx.x;
    const int tconv = d_tconv;

    for (int i = tid; i < CLEN*100; i += blockDim.x) {
        int l = i / 100, e = i % 100;
        int tc = min(chunk*CLEN + l, tconv);
        sA[i] = d_Amat[tc*100 + e];
        sK[i] = d_Kmat[tc*100 + e];
    }
    __syncthreads();

    const int warpId = tid / 32, lane = tid % 32;
    const int sub = lane / 10, row = lane - sub*10;
    const int g = slice*24 + warpId*3 + sub;
    const bool valid = (lane < 30) && (g < NTRAJ);
    const int traj = valid ? g : 0;

    float x = d_Xst[((size_t)chunk*NTRAJ + traj)*NS + row];

    const bool wr = valid && (out_size >= OUT_TRAJ_SIZE);
    float errsum = 0.f;
    const float* yb = Y + (size_t)traj * (T_STEPS*NS);
    const float* xb = X + (size_t)traj * TRAJ_STRIDE;
    float* ob = out + (size_t)traj * TRAJ_STRIDE;

    #pragma unroll
    for (int l = 0; l < CLEN; ++l) {
        const int t = chunk*CLEN + l;
        float y = yb[t*10 + row];
        x = group_step(&sK[l*100], &sA[l*100], y, x, sub, row);
        if (wr) ob[(t+1)*10 + row] = x;
        float d = xb[(t+1)*10 + row] - x;
        errsum += d * d;
    }

    float tot = 0.f;
    #pragma unroll
    for (int j = 0; j < 10; ++j)
        tot += __shfl_sync(0xffffffffu, errsum, sub*10 + j);
    if (valid && row == 0)
        d_partial[(size_t)chunk*NTRAJ + traj] = tot;
}

// ============================================================================
// Kernel 5: mse — 1024 threads, 4 lanes per trajectory (25 coalesced loads
// each), shfl reduce within 4-lane group, block tree over 256 dB values.
// ============================================================================
__global__ __launch_bounds__(1024) void mse_kernel(float* __restrict__ out, int out_size)
{
    __shared__ float red[NTRAJ];
    const int tid = threadIdx.x;
    const int traj = tid >> 2;
    const int lane4 = tid & 3;

    float s = 0.f;
    #pragma unroll
    for (int c = 0; c < CHUNKS/4; ++c)
        s += d_partial[(size_t)(c*4 + lane4)*NTRAJ + traj];
    s += __shfl_xor_sync(0xffffffffu, s, 1);
    s += __shfl_xor_sync(0xffffffffu, s, 2);
    if (lane4 == 0)
        red[traj] = 10.f * log10f(s / (float)(T_STEPS * NS));
    __syncthreads();
    for (int off = NTRAJ/2; off > 0; off >>= 1) {
        if (tid < off) red[tid] += red[tid + off];
        __syncthreads();
    }
    if (tid == 0 && OUT_MSE_OFF < out_size)
        out[OUT_MSE_OFF] = red[0] / (float)NTRAJ;
}

// ============================================================================
extern "C" void kernel_launch(void* const* d_in, const int* in_sizes, int n_in,
                              void* d_out, int out_size)
{
    const float* X = (const float*)d_in[0];
    const float* Y = (const float*)d_in[1];
    const float* F = (const float*)d_in[2];
    const float* H = (const float*)d_in[3];
    const float* Q = (const float*)d_in[4];
    const float* R = (const float*)d_in[5];
    float* out = (float*)d_out;

    riccati_kernel  <<<1, 128>>>(F, H, Q, R);
    fused_mid_kernel<<<NB_MID, 256>>>(Y, out, out_size);
    chainscan_kernel<<<11, 256>>>();
    replay_kernel   <<<dim3(CHUNKS, 11), 256>>>(Y, X, out, out_size);
    mse_kernel      <<<1, 1024>>>(out, out_size);
}